// round 16
// baseline (speedup 1.0000x reference)
#include <cuda_runtime.h>
#include <cuda_fp16.h>
#include <math.h>
#include <stdint.h>

#define HEADS  16
#define DHEAD  128
#define BATCH  2
#define SEQ    2048
#define DIM    2048
#define INNER  (HEADS * DHEAD)   // 2048
#define BH     (BATCH * HEADS)   // 32
#define QSCALE 0.088388347648318447f

// ---------------- scratch (allocation-free: __device__ globals) ----------------
__device__ __half g_xh    [(size_t)BATCH * SEQ * DIM];
__device__ __half g_Wqkvh [(size_t)DIM * 3 * INNER];    // [K, 3N]: Wq | Wkv
__device__ __half g_Woh   [(size_t)INNER * DIM];
__device__ float  g_ctab  [(size_t)SEQ * DHEAD];
__device__ float  g_stab  [(size_t)SEQ * DHEAD];
__device__ __half g_qkvlin[(size_t)BATCH * SEQ * 3 * INNER];  // rotary pre-applied to q,k
__device__ __half g_attnh [(size_t)BATCH * SEQ * INNER];

__device__ __forceinline__ uint32_t pack2(float a, float b) {
    __half2 h = __floats2half2_rn(a, b);
    return *reinterpret_cast<uint32_t*>(&h);
}

#define MMA_F16(C, A0, A1, A2, A3, B0, B1)                                    \
    asm volatile(                                                             \
        "mma.sync.aligned.m16n8k16.row.col.f32.f16.f16.f32 "                  \
        "{%0,%1,%2,%3}, {%4,%5,%6,%7}, {%8,%9}, {%0,%1,%2,%3};"               \
        : "+f"((C)[0]), "+f"((C)[1]), "+f"((C)[2]), "+f"((C)[3])              \
        : "r"(A0), "r"(A1), "r"(A2), "r"(A3), "r"(B0), "r"(B1))

#define LDSM4(R0, R1, R2, R3, ADDR)                                           \
    asm volatile("ldmatrix.sync.aligned.m8n8.x4.shared.b16 {%0,%1,%2,%3},[%4];" \
                 : "=r"(R0), "=r"(R1), "=r"(R2), "=r"(R3) : "r"(ADDR))

#define LDSM4T(R0, R1, R2, R3, ADDR)                                          \
    asm volatile("ldmatrix.sync.aligned.m8n8.x4.trans.shared.b16 {%0,%1,%2,%3},[%4];" \
                 : "=r"(R0), "=r"(R1), "=r"(R2), "=r"(R3) : "r"(ADDR))

#define CPA16(dst, src)                                                       \
    asm volatile("cp.async.cg.shared.global [%0], [%1], 16;"                  \
                 :: "r"(dst), "l"(src))

// ------- fused fp32 -> fp16 conversion; Wq/Wkv interleave into combined [K, 3N] -------
#define CV_S0 (BATCH * SEQ * DIM / 4)
#define CV_S1 (DIM * INNER / 4)
#define CV_S2 (DIM * 2 * INNER / 4)
#define CV_S3 (INNER * DIM / 4)
#define CV_TOT (CV_S0 + CV_S1 + CV_S2 + CV_S3)
__global__ __launch_bounds__(256) void cvt4_kernel(
    const float4* __restrict__ x,  uint2* __restrict__ xh,
    const float4* __restrict__ wq, const float4* __restrict__ wk,
    uint2* __restrict__ wqkvh,
    const float4* __restrict__ wo, uint2* __restrict__ woh)
{
    int base = blockIdx.x * 256 + threadIdx.x;
    const int stride = gridDim.x * 256;
    const float4* s[4]; uint2* d[4];
    #pragma unroll
    for (int u = 0; u < 4; u++) {
        int i = base + u * stride;
        if (i < CV_S0) {
            s[u] = x + i; d[u] = xh + i;
        } else if (i < CV_S0 + CV_S1) {
            int j = i - CV_S0;
            int k = j >> 9, c = j & 511;
            s[u] = wq + j; d[u] = wqkvh + k * 1536 + c;
        } else if (i < CV_S0 + CV_S1 + CV_S2) {
            int j = i - CV_S0 - CV_S1;
            int k = j >> 10, c = j & 1023;
            s[u] = wk + j; d[u] = wqkvh + k * 1536 + 512 + c;
        } else {
            int j = i - CV_S0 - CV_S1 - CV_S2;
            s[u] = wo + j; d[u] = woh + j;
        }
    }
    float4 v[4];
    #pragma unroll
    for (int u = 0; u < 4; u++) v[u] = *s[u];
    #pragma unroll
    for (int u = 0; u < 4; u++)
        *d[u] = make_uint2(pack2(v[u].x, v[u].y), pack2(v[u].z, v[u].w));
}

// ---------------- cos/sin tables from rotary_emb (computed ONCE) ----------------
__global__ __launch_bounds__(256) void rottab_kernel(
    const float* __restrict__ rot, float* __restrict__ ctab, float* __restrict__ stab)
{
    int i = blockIdx.x * blockDim.x + threadIdx.x;
    float s, c;
    sincosf(rot[i], &s, &c);
    ctab[i] = c;
    stab[i] = s;
}

// ---------------- fp16 GEMM, m16n8k16 + ldmatrix, 4-stage cp.async, top-issue ----------------
// MODE 0: fp32 out + bias. MODE 1: fp16 out with fused rotary (q/k regions) into qkvlin.
#define HG_PA 40
#define HG_PB 136
#define HG_ASTR (128 * HG_PA)
#define HG_BSTR (32 * HG_PB)
#define HG_NSTG 4
#define HG_BOFF (HG_NSTG * HG_ASTR)
#define HG_SMEM ((HG_NSTG * HG_ASTR + HG_NSTG * HG_BSTR) * 2)   // 75776 B

template<int MODE>
__global__ __launch_bounds__(256, 2) void hgemm_kernel(
    const __half* __restrict__ A, const __half* __restrict__ Bm,
    void* __restrict__ Cv, int M, int Nn, int K, int ldc,
    const float* __restrict__ bias,
    const float* __restrict__ ctab, const float* __restrict__ stab)
{
    extern __shared__ __half smh[];
    __half* As = smh;
    __half* Bs = smh + HG_BOFF;
    const uint32_t as_u = (uint32_t)__cvta_generic_to_shared(As);
    const uint32_t bs_u = (uint32_t)__cvta_generic_to_shared(Bs);

    const int bx = blockIdx.x, by = blockIdx.y;
    const int tid  = threadIdx.x;
    const int lane = tid & 31;
    const int wid  = tid >> 5;
    const int warpm = wid >> 2;
    const int warpn = wid & 3;
    const int grp = lane >> 2;
    const int tig = lane & 3;

    const __half* Ag = A  + (long long)by * 128 * K;
    const __half* Bg = Bm + bx * 128;

    const int T = K >> 5;

    auto issue = [&](int t, int st) {
        int kt = t * 32;
        #pragma unroll
        for (int i = 0; i < 2; i++) {
            int c = tid + 256 * i;
            int row = c >> 2, cc = (c & 3) * 8;
            uint32_t d = as_u + (st * HG_ASTR + row * HG_PA + cc) * 2;
            CPA16(d, Ag + (long long)row * K + kt + cc);
        }
        #pragma unroll
        for (int i = 0; i < 2; i++) {
            int c = tid + 256 * i;
            int row = c >> 4, cc = (c & 15) * 8;
            uint32_t d = bs_u + (st * HG_BSTR + row * HG_PB + cc) * 2;
            CPA16(d, Bg + (long long)(kt + row) * Nn + cc);
        }
        asm volatile("cp.async.commit_group;");
    };

    float c[4][4][4];
    #pragma unroll
    for (int i = 0; i < 4; i++)
        #pragma unroll
        for (int j = 0; j < 4; j++)
            #pragma unroll
            for (int r = 0; r < 4; r++) c[i][j][r] = 0.0f;

    issue(0, 0);
    issue(1, 1);
    issue(2, 2);

    for (int t = 0; t < T; t++) {
        if (t < T - 2)       asm volatile("cp.async.wait_group 2;");
        else if (t == T - 2) asm volatile("cp.async.wait_group 1;");
        else                 asm volatile("cp.async.wait_group 0;");
        __syncthreads();
        if (t + 3 < T) issue(t + 3, (t + 3) & 3);

        const uint32_t asb = as_u + (t & 3) * HG_ASTR * 2;
        const uint32_t bsb = bs_u + (t & 3) * HG_BSTR * 2;

        #pragma unroll
        for (int s = 0; s < 2; s++) {
            const int ks = s * 16;
            uint32_t a[4][4];
            #pragma unroll
            for (int im = 0; im < 4; im++) {
                int row = warpm * 64 + im * 16 + (lane & 15);
                uint32_t ad = asb + (row * HG_PA + ks + ((lane >> 4) * 8)) * 2;
                LDSM4(a[im][0], a[im][1], a[im][2], a[im][3], ad);
            }
            uint32_t bb[4][2];
            #pragma unroll
            for (int ib = 0; ib < 2; ib++) {
                int row = ks + (lane & 15);
                int col = warpn * 32 + ib * 16 + ((lane >> 4) * 8);
                uint32_t bd = bsb + (row * HG_PB + col) * 2;
                LDSM4T(bb[2 * ib][0], bb[2 * ib][1], bb[2 * ib + 1][0], bb[2 * ib + 1][1], bd);
            }
            #pragma unroll
            for (int im = 0; im < 4; im++)
                #pragma unroll
                for (int jn = 0; jn < 4; jn++)
                    MMA_F16(c[im][jn], a[im][0], a[im][1], a[im][2], a[im][3],
                            bb[jn][0], bb[jn][1]);
        }
    }

    // region: 0=q (rotary+scale), 1=k (rotary), 2=v (plain). CTA-uniform.
    const int region = (MODE == 1) ? (bx >> 4) : 0;

    #pragma unroll
    for (int im = 0; im < 4; im++) {
        int row0 = by * 128 + warpm * 64 + im * 16 + grp;
        #pragma unroll
        for (int jn = 0; jn < 4; jn++) {
            int col0 = bx * 128 + warpn * 32 + jn * 8 + 2 * tig;
            if (MODE == 0) {
                float* C = (float*)Cv;
                float2 v0 = make_float2(c[im][jn][0], c[im][jn][1]);
                float2 v1 = make_float2(c[im][jn][2], c[im][jn][3]);
                v0.x += bias[col0]; v0.y += bias[col0 + 1];
                v1.x += bias[col0]; v1.y += bias[col0 + 1];
                *(float2*)(C + (long long)row0 * ldc + col0)       = v0;
                *(float2*)(C + (long long)(row0 + 8) * ldc + col0) = v1;
            } else {
                __half* C = (__half*)Cv;
                if (region == 2) {
                    *(__half2*)(C + (long long)row0 * ldc + col0) =
                        __floats2half2_rn(c[im][jn][0], c[im][jn][1]);
                    *(__half2*)(C + (long long)(row0 + 8) * ldc + col0) =
                        __floats2half2_rn(c[im][jn][2], c[im][jn][3]);
                } else {
                    const int d0 = col0 & (DHEAD - 1);
                    #pragma unroll
                    for (int hf = 0; hf < 2; hf++) {
                        int r = row0 + 8 * hf;
                        int n = r & (SEQ - 1);
                        float v0 = c[im][jn][2 * hf], v1 = c[im][jn][2 * hf + 1];
                        float2 cs = *(const float2*)&ctab[n * DHEAD + d0];
                        float2 sn = *(const float2*)&stab[n * DHEAD + d0];
                        float o0 = v0 * cs.x - v1 * sn.x;
                        float o1 = v1 * cs.y + v0 * sn.y;
                        if (region == 0) { o0 *= QSCALE; o1 *= QSCALE; }
                        *(__half2*)(C + (long long)r * ldc + col0) =
                            __floats2half2_rn(o0, o1);
                    }
                }
            }
        }
    }
}

// ------- fused flash attention: 256 thr, Q-block 128, KV-tile 32, 2 CTAs/SM -------
// Q/K/V ALL read directly from combined qkvlin (stride 3*INNER); rotary pre-applied.
#define FPQ 136
#define FPK 136
#define QROWS 128
#define KT 32
#define VSTRIDE (3 * INNER)
#define FKS_STR (KT * FPK)
#define FVS_STR (KT * FPK)
#define FQS_SZ  (QROWS * FPQ)
#define FL_KOFF FQS_SZ
#define FL_VOFF (FQS_SZ + 3 * FKS_STR)
#define FLASH_SMEM ((FQS_SZ + 3 * FKS_STR + 3 * FVS_STR) * 2)   // 87040 B
#define NTILE (SEQ / KT)

__global__ __launch_bounds__(256, 2) void flash_kernel(
    const __half* __restrict__ qkvlin, __half* __restrict__ attn)
{
    extern __shared__ __half fsm[];
    __half* Qs = fsm;
    const uint32_t qs_u = (uint32_t)__cvta_generic_to_shared(Qs);
    const uint32_t ks_u = qs_u + FL_KOFF * 2;
    const uint32_t vs_u = qs_u + FL_VOFF * 2;

    const int qblk = blockIdx.x, bh = blockIdx.y;
    const int b = bh >> 4, h = bh & 15;
    const int tid = threadIdx.x, lane = tid & 31, wid = tid >> 5;
    const int grp = lane >> 2, tig = lane & 3;

    const __half* base = qkvlin + ((long long)b * SEQ) * VSTRIDE + h * DHEAD;
    const __half* Qg = base + (long long)qblk * QROWS * VSTRIDE;           // q region
    const __half* Kg = base + INNER;                                       // k region
    const __half* Vg = base + 2 * INNER;                                   // v region

    auto issue = [&](int it, int buf) {
        #pragma unroll
        for (int i = 0; i < 2; i++) {
            int ch = tid + 256 * i;
            int row = ch >> 4, cc = (ch & 15) * 8;
            uint32_t d = ks_u + (buf * FKS_STR + row * FPK + cc) * 2;
            CPA16(d, Kg + (long long)(it * KT + row) * VSTRIDE + cc);
        }
        #pragma unroll
        for (int i = 0; i < 2; i++) {
            int ch = tid + 256 * i;
            int row = ch >> 4, cc = (ch & 15) * 8;
            uint32_t d = vs_u + (buf * FVS_STR + row * FPK + cc) * 2;
            CPA16(d, Vg + (long long)(it * KT + row) * VSTRIDE + cc);
        }
        asm volatile("cp.async.commit_group;");
    };

    issue(0, 0);
    issue(1, 1);

    #pragma unroll
    for (int i = 0; i < 8; i++) {
        int ch = tid + 256 * i;
        int row = ch >> 4, cc = (ch & 15) * 8;
        *(uint4*)&Qs[row * FPQ + cc] = *(const uint4*)(Qg + (long long)row * VSTRIDE + cc);
    }

    float o[16][4];
    #pragma unroll
    for (int f = 0; f < 16; f++)
        #pragma unroll
        for (int r = 0; r < 4; r++) o[f][r] = 0.0f;
    float l0 = 0.0f, l1 = 0.0f;

    for (int it = 0; it < NTILE; it++) {
        if (it < NTILE - 1) asm volatile("cp.async.wait_group 1;");
        else                asm volatile("cp.async.wait_group 0;");
        __syncthreads();
        if (it + 2 < NTILE) issue(it + 2, (it + 2) % 3);

        const uint32_t kb = ks_u + (it % 3) * FKS_STR * 2;
        const uint32_t vb = vs_u + (it % 3) * FVS_STR * 2;

        float sc[4][4];
        #pragma unroll
        for (int f = 0; f < 4; f++)
            #pragma unroll
            for (int r = 0; r < 4; r++) sc[f][r] = 0.0f;

        #pragma unroll
        for (int s = 0; s < 8; s++) {
            const int ks = s * 16;
            uint32_t a0, a1, a2, a3;
            {
                int row = wid * 16 + (lane & 15);
                uint32_t ad = qs_u + (row * FPQ + ks + ((lane >> 4) * 8)) * 2;
                LDSM4(a0, a1, a2, a3, ad);
            }
            #pragma unroll
            for (int pf = 0; pf < 2; pf++) {
                int j = lane >> 3;
                int krow = pf * 16 + ((j >> 1) * 8) + (lane & 7);
                uint32_t bd = kb + (krow * FPK + ks + ((j & 1) * 8)) * 2;
                uint32_t r0, r1, r2, r3;
                LDSM4(r0, r1, r2, r3, bd);
                MMA_F16(sc[2 * pf],     a0, a1, a2, a3, r0, r1);
                MMA_F16(sc[2 * pf + 1], a0, a1, a2, a3, r2, r3);
            }
        }

        float rs0 = 0.0f, rs1 = 0.0f;
        #pragma unroll
        for (int f = 0; f < 4; f++) {
            sc[f][0] = __expf(sc[f][0]);
            sc[f][1] = __expf(sc[f][1]);
            sc[f][2] = __expf(sc[f][2]);
            sc[f][3] = __expf(sc[f][3]);
            rs0 += sc[f][0] + sc[f][1];
            rs1 += sc[f][2] + sc[f][3];
        }
        rs0 += __shfl_xor_sync(0xffffffffu, rs0, 1);
        rs0 += __shfl_xor_sync(0xffffffffu, rs0, 2);
        rs1 += __shfl_xor_sync(0xffffffffu, rs1, 1);
        rs1 += __shfl_xor_sync(0xffffffffu, rs1, 2);
        l0 += rs0; l1 += rs1;

        #pragma unroll
        for (int s = 0; s < 2; s++) {
            uint32_t a0 = pack2(sc[2 * s][0],     sc[2 * s][1]);
            uint32_t a1 = pack2(sc[2 * s][2],     sc[2 * s][3]);
            uint32_t a2 = pack2(sc[2 * s + 1][0], sc[2 * s + 1][1]);
            uint32_t a3 = pack2(sc[2 * s + 1][2], sc[2 * s + 1][3]);
            #pragma unroll
            for (int pf = 0; pf < 8; pf++) {
                int row = s * 16 + (lane & 15);
                int col = pf * 16 + ((lane >> 4) * 8);
                uint32_t bd = vb + (row * FPK + col) * 2;
                uint32_t r0, r1, r2, r3;
                LDSM4T(r0, r1, r2, r3, bd);
                MMA_F16(o[2 * pf],     a0, a1, a2, a3, r0, r1);
                MMA_F16(o[2 * pf + 1], a0, a1, a2, a3, r2, r3);
            }
        }
    }

    float inv0 = 1.0f / l0, inv1 = 1.0f / l1;
    int nrow = qblk * QROWS + 16 * wid + grp;
    __half* outp = attn + ((long long)(b * SEQ + nrow)) * INNER + h * DHEAD;
    #pragma unroll
    for (int f = 0; f < 16; f++) {
        int col = 8 * f + 2 * tig;
        *(__half2*)(outp + col) = __floats2half2_rn(o[f][0] * inv0, o[f][1] * inv0);
        *(__half2*)(outp + (long long)8 * INNER + col) =
            __floats2half2_rn(o[f][2] * inv1, o[f][3] * inv1);
    }
}

// ---------------- launch ----------------
extern "C" void kernel_launch(void* const* d_in, const int* in_sizes, int n_in,
                              void* d_out, int out_size)
{
    const float* x   = (const float*)d_in[0];
    const float* rot = (const float*)d_in[1];
    const float* Wq  = (const float*)d_in[2];
    const float* Wkv = (const float*)d_in[3];
    const float* Wo  = (const float*)d_in[4];
    const float* bo  = (const float*)d_in[5];
    float* out = (float*)d_out;

    __half *xh, *Wqkvh, *Woh, *qkvlin, *attnh;
    float *ctab, *stab;
    cudaGetSymbolAddress((void**)&xh,     g_xh);
    cudaGetSymbolAddress((void**)&Wqkvh,  g_Wqkvh);
    cudaGetSymbolAddress((void**)&Woh,    g_Woh);
    cudaGetSymbolAddress((void**)&ctab,   g_ctab);
    cudaGetSymbolAddress((void**)&stab,   g_stab);
    cudaGetSymbolAddress((void**)&qkvlin, g_qkvlin);
    cudaGetSymbolAddress((void**)&attnh,  g_attnh);

    cudaFuncSetAttribute(flash_kernel,
                         cudaFuncAttributeMaxDynamicSharedMemorySize, FLASH_SMEM);
    cudaFuncSetAttribute(hgemm_kernel<0>,
                         cudaFuncAttributeMaxDynamicSharedMemorySize, HG_SMEM);
    cudaFuncSetAttribute(hgemm_kernel<1>,
                         cudaFuncAttributeMaxDynamicSharedMemorySize, HG_SMEM);

    dim3 blk(256);
    const int M = BATCH * SEQ;   // 4096

    // 0) convert all inputs to fp16 (Wq/Wkv interleaved into combined [K,3N]); rotary tables
    cvt4_kernel<<<CV_TOT / (256 * 4), blk>>>(
        (const float4*)x,   (uint2*)xh,
        (const float4*)Wq,  (const float4*)Wkv, (uint2*)Wqkvh,
        (const float4*)Wo,  (uint2*)Woh);
    rottab_kernel<<<(SEQ * DHEAD) / 256, blk>>>(rot, ctab, stab);

    // 1) qkv_lin = xh @ [Wq|Wkv], rotary fused into epilogue (q scaled, k rotated, v plain)
    hgemm_kernel<1><<<dim3(3 * INNER / 128, M / 128), blk, HG_SMEM>>>(
        xh, Wqkvh, qkvlin, M, 3 * INNER, DIM, 3 * INNER, nullptr, ctab, stab);

    // 2) fused attention -> attnh; Q/K/V all from qkvlin
    flash_kernel<<<dim3(SEQ / QROWS, BH), blk, FLASH_SMEM>>>(qkvlin, attnh);

    // 3) out = attnh @ Woh + bo  (fp32 out)
    hgemm_kernel<0><<<dim3(DIM / 128, M / 128), blk, HG_SMEM>>>(
        attnh, Woh, out, M, DIM, INNER, DIM, bo, nullptr, nullptr);
}

// round 17
// speedup vs baseline: 1.0305x; 1.0305x over previous
#include <cuda_runtime.h>
#include <cuda_fp16.h>
#include <math.h>
#include <stdint.h>

#define HEADS  16
#define DHEAD  128
#define BATCH  2
#define SEQ    2048
#define DIM    2048
#define INNER  (HEADS * DHEAD)   // 2048
#define BH     (BATCH * HEADS)   // 32
#define L2E    1.4426950408889634f

// ---------------- scratch (allocation-free: __device__ globals) ----------------
__device__ __half g_xh    [(size_t)BATCH * SEQ * DIM];
__device__ __half g_Wqkvh [(size_t)DIM * 3 * INNER];    // [K, 3N]: Wq | Wkv
__device__ __half g_Woh   [(size_t)INNER * DIM];
__device__ float  g_ctab  [(size_t)SEQ * DHEAD];
__device__ float  g_stab  [(size_t)SEQ * DHEAD];
__device__ __half g_qkvlin[(size_t)BATCH * SEQ * 3 * INNER];
__device__ __half g_Qh    [(size_t)BH * SEQ * DHEAD];
__device__ __half g_Kh    [(size_t)BH * SEQ * DHEAD];
__device__ __half g_attnh [(size_t)BATCH * SEQ * INNER];

__device__ __forceinline__ uint32_t pack2(float a, float b) {
    __half2 h = __floats2half2_rn(a, b);
    return *reinterpret_cast<uint32_t*>(&h);
}

#define MMA_F16(C, A0, A1, A2, A3, B0, B1)                                    \
    asm volatile(                                                             \
        "mma.sync.aligned.m16n8k16.row.col.f32.f16.f16.f32 "                  \
        "{%0,%1,%2,%3}, {%4,%5,%6,%7}, {%8,%9}, {%0,%1,%2,%3};"               \
        : "+f"((C)[0]), "+f"((C)[1]), "+f"((C)[2]), "+f"((C)[3])              \
        : "r"(A0), "r"(A1), "r"(A2), "r"(A3), "r"(B0), "r"(B1))

#define LDSM4(R0, R1, R2, R3, ADDR)                                           \
    asm volatile("ldmatrix.sync.aligned.m8n8.x4.shared.b16 {%0,%1,%2,%3},[%4];" \
                 : "=r"(R0), "=r"(R1), "=r"(R2), "=r"(R3) : "r"(ADDR))

#define LDSM4T(R0, R1, R2, R3, ADDR)                                          \
    asm volatile("ldmatrix.sync.aligned.m8n8.x4.trans.shared.b16 {%0,%1,%2,%3},[%4];" \
                 : "=r"(R0), "=r"(R1), "=r"(R2), "=r"(R3) : "r"(ADDR))

#define CPA16(dst, src)                                                       \
    asm volatile("cp.async.cg.shared.global [%0], [%1], 16;"                  \
                 :: "r"(dst), "l"(src))

// ------- fused fp32 -> fp16 conversion; Wq/Wkv interleave into combined [K, 3N] -------
#define CV_S0 (BATCH * SEQ * DIM / 4)
#define CV_S1 (DIM * INNER / 4)
#define CV_S2 (DIM * 2 * INNER / 4)
#define CV_S3 (INNER * DIM / 4)
#define CV_TOT (CV_S0 + CV_S1 + CV_S2 + CV_S3)
__global__ __launch_bounds__(256) void cvt4_kernel(
    const float4* __restrict__ x,  uint2* __restrict__ xh,
    const float4* __restrict__ wq, const float4* __restrict__ wk,
    uint2* __restrict__ wqkvh,
    const float4* __restrict__ wo, uint2* __restrict__ woh)
{
    int base = blockIdx.x * 256 + threadIdx.x;
    const int stride = gridDim.x * 256;
    const float4* s[4]; uint2* d[4];
    #pragma unroll
    for (int u = 0; u < 4; u++) {
        int i = base + u * stride;
        if (i < CV_S0) {
            s[u] = x + i; d[u] = xh + i;
        } else if (i < CV_S0 + CV_S1) {
            int j = i - CV_S0;
            int k = j >> 9, c = j & 511;
            s[u] = wq + j; d[u] = wqkvh + k * 1536 + c;
        } else if (i < CV_S0 + CV_S1 + CV_S2) {
            int j = i - CV_S0 - CV_S1;
            int k = j >> 10, c = j & 1023;
            s[u] = wk + j; d[u] = wqkvh + k * 1536 + 512 + c;
        } else {
            int j = i - CV_S0 - CV_S1 - CV_S2;
            s[u] = wo + j; d[u] = woh + j;
        }
    }
    float4 v[4];
    #pragma unroll
    for (int u = 0; u < 4; u++) v[u] = *s[u];
    #pragma unroll
    for (int u = 0; u < 4; u++)
        *d[u] = make_uint2(pack2(v[u].x, v[u].y), pack2(v[u].z, v[u].w));
}

// ---------------- cos/sin tables from rotary_emb (computed ONCE) ----------------
__global__ __launch_bounds__(256) void rottab_kernel(
    const float* __restrict__ rot, float* __restrict__ ctab, float* __restrict__ stab)
{
    int i = blockIdx.x * blockDim.x + threadIdx.x;
    float s, c;
    sincosf(rot[i], &s, &c);
    ctab[i] = c;
    stab[i] = s;
}

// ---------------- fp16 GEMM, m16n8k16 + ldmatrix, 4-stage cp.async, top-issue ----------------
// MODE 0: fp32 out + bias. MODE 1: fp16 out.
#define HG_PA 40
#define HG_PB 136
#define HG_ASTR (128 * HG_PA)
#define HG_BSTR (32 * HG_PB)
#define HG_NSTG 4
#define HG_BOFF (HG_NSTG * HG_ASTR)
#define HG_SMEM ((HG_NSTG * HG_ASTR + HG_NSTG * HG_BSTR) * 2)   // 75776 B

template<int MODE>
__global__ __launch_bounds__(256, 2) void hgemm_kernel(
    const __half* __restrict__ A, const __half* __restrict__ Bm,
    void* __restrict__ Cv, int M, int Nn, int K, int ldc,
    const float* __restrict__ bias)
{
    extern __shared__ __half smh[];
    __half* As = smh;
    __half* Bs = smh + HG_BOFF;
    const uint32_t as_u = (uint32_t)__cvta_generic_to_shared(As);
    const uint32_t bs_u = (uint32_t)__cvta_generic_to_shared(Bs);

    const int bx = blockIdx.x, by = blockIdx.y;
    const int tid  = threadIdx.x;
    const int lane = tid & 31;
    const int wid  = tid >> 5;
    const int warpm = wid >> 2;
    const int warpn = wid & 3;
    const int grp = lane >> 2;
    const int tig = lane & 3;

    const __half* Ag = A  + (long long)by * 128 * K;
    const __half* Bg = Bm + bx * 128;

    const int T = K >> 5;

    auto issue = [&](int t, int st) {
        int kt = t * 32;
        #pragma unroll
        for (int i = 0; i < 2; i++) {
            int c = tid + 256 * i;
            int row = c >> 2, cc = (c & 3) * 8;
            uint32_t d = as_u + (st * HG_ASTR + row * HG_PA + cc) * 2;
            CPA16(d, Ag + (long long)row * K + kt + cc);
        }
        #pragma unroll
        for (int i = 0; i < 2; i++) {
            int c = tid + 256 * i;
            int row = c >> 4, cc = (c & 15) * 8;
            uint32_t d = bs_u + (st * HG_BSTR + row * HG_PB + cc) * 2;
            CPA16(d, Bg + (long long)(kt + row) * Nn + cc);
        }
        asm volatile("cp.async.commit_group;");
    };

    float c[4][4][4];
    #pragma unroll
    for (int i = 0; i < 4; i++)
        #pragma unroll
        for (int j = 0; j < 4; j++)
            #pragma unroll
            for (int r = 0; r < 4; r++) c[i][j][r] = 0.0f;

    issue(0, 0);
    issue(1, 1);
    issue(2, 2);

    for (int t = 0; t < T; t++) {
        if (t < T - 2)       asm volatile("cp.async.wait_group 2;");
        else if (t == T - 2) asm volatile("cp.async.wait_group 1;");
        else                 asm volatile("cp.async.wait_group 0;");
        __syncthreads();
        if (t + 3 < T) issue(t + 3, (t + 3) & 3);

        const uint32_t asb = as_u + (t & 3) * HG_ASTR * 2;
        const uint32_t bsb = bs_u + (t & 3) * HG_BSTR * 2;

        #pragma unroll
        for (int s = 0; s < 2; s++) {
            const int ks = s * 16;
            uint32_t a[4][4];
            #pragma unroll
            for (int im = 0; im < 4; im++) {
                int row = warpm * 64 + im * 16 + (lane & 15);
                uint32_t ad = asb + (row * HG_PA + ks + ((lane >> 4) * 8)) * 2;
                LDSM4(a[im][0], a[im][1], a[im][2], a[im][3], ad);
            }
            uint32_t bb[4][2];
            #pragma unroll
            for (int ib = 0; ib < 2; ib++) {
                int row = ks + (lane & 15);
                int col = warpn * 32 + ib * 16 + ((lane >> 4) * 8);
                uint32_t bd = bsb + (row * HG_PB + col) * 2;
                LDSM4T(bb[2 * ib][0], bb[2 * ib][1], bb[2 * ib + 1][0], bb[2 * ib + 1][1], bd);
            }
            #pragma unroll
            for (int im = 0; im < 4; im++)
                #pragma unroll
                for (int jn = 0; jn < 4; jn++)
                    MMA_F16(c[im][jn], a[im][0], a[im][1], a[im][2], a[im][3],
                            bb[jn][0], bb[jn][1]);
        }
    }

    #pragma unroll
    for (int im = 0; im < 4; im++) {
        int row0 = by * 128 + warpm * 64 + im * 16 + grp;
        #pragma unroll
        for (int jn = 0; jn < 4; jn++) {
            int col0 = bx * 128 + warpn * 32 + jn * 8 + 2 * tig;
            if (MODE == 0) {
                float* C = (float*)Cv;
                float2 v0 = make_float2(c[im][jn][0], c[im][jn][1]);
                float2 v1 = make_float2(c[im][jn][2], c[im][jn][3]);
                v0.x += bias[col0]; v0.y += bias[col0 + 1];
                v1.x += bias[col0]; v1.y += bias[col0 + 1];
                *(float2*)(C + (long long)row0 * ldc + col0)       = v0;
                *(float2*)(C + (long long)(row0 + 8) * ldc + col0) = v1;
            } else {
                __half* C = (__half*)Cv;
                *(__half2*)(C + (long long)row0 * ldc + col0) =
                    __floats2half2_rn(c[im][jn][0], c[im][jn][1]);
                *(__half2*)(C + (long long)(row0 + 8) * ldc + col0) =
                    __floats2half2_rn(c[im][jn][2], c[im][jn][3]);
            }
        }
    }
}

// ------- rotary + scale + head split, 4 pairs (16 B) per thread -------
__device__ __forceinline__ uint32_t rotpair(uint32_t qh, float c0, float c1,
                                            float s0, float s1, float scale) {
    float2 q = __half22float2(*reinterpret_cast<__half2*>(&qh));
    return pack2((q.x * c0 - q.y * s0) * scale, (q.y * c1 + q.x * s1) * scale);
}

__global__ __launch_bounds__(256) void rotary_kernel(
    const __half* __restrict__ qkvlin,
    const float* __restrict__ ctab, const float* __restrict__ stab,
    __half* __restrict__ Q, __half* __restrict__ K)
{
    int idx = blockIdx.x * 256 + threadIdx.x;    // BATCH*SEQ*HEADS*16
    int g = idx & 15;                 // 4-pair group within head (8 halves)
    int h = (idx >> 4) & (HEADS - 1);
    int n = (idx >> 8) & (SEQ - 1);
    int b = idx >> 19;
    int d0 = g * 8;

    const __half* rowp = qkvlin + ((long long)(b * SEQ + n)) * (3 * INNER) + h * DHEAD + d0;
    uint4 qv = *(const uint4*)rowp;
    uint4 kv = *(const uint4*)(rowp + INNER);

    const float* cp = &ctab[n * DHEAD + d0];
    const float* sp = &stab[n * DHEAD + d0];
    float4 cs0 = *(const float4*)cp,     cs1 = *(const float4*)(cp + 4);
    float4 sn0 = *(const float4*)sp,     sn1 = *(const float4*)(sp + 4);

    const float scale = 0.088388347648318447f;
    long long bh = (long long)b * HEADS + h;

    uint4 qo, ko;
    qo.x = rotpair(qv.x, cs0.x, cs0.y, sn0.x, sn0.y, scale);
    qo.y = rotpair(qv.y, cs0.z, cs0.w, sn0.z, sn0.w, scale);
    qo.z = rotpair(qv.z, cs1.x, cs1.y, sn1.x, sn1.y, scale);
    qo.w = rotpair(qv.w, cs1.z, cs1.w, sn1.z, sn1.w, scale);
    ko.x = rotpair(kv.x, cs0.x, cs0.y, sn0.x, sn0.y, 1.0f);
    ko.y = rotpair(kv.y, cs0.z, cs0.w, sn0.z, sn0.w, 1.0f);
    ko.z = rotpair(kv.z, cs1.x, cs1.y, sn1.x, sn1.y, 1.0f);
    ko.w = rotpair(kv.w, cs1.z, cs1.w, sn1.z, sn1.w, 1.0f);

    *(uint4*)(Q + (bh * SEQ + n) * DHEAD + d0) = qo;
    *(uint4*)(K + (bh * SEQ + n) * DHEAD + d0) = ko;
}

// ------- fused flash attention: 256 thr, Q-block 128, KV-tile 32, 2 CTAs/SM -------
// No-max softmax via ex2.approx.f16x2; V read directly from qkvlin (stride 3*INNER).
#define FPQ 136
#define FPK 136
#define QROWS 128
#define KT 32
#define VSTRIDE (3 * INNER)
#define FKS_STR (KT * FPK)
#define FVS_STR (KT * FPK)
#define FQS_SZ  (QROWS * FPQ)
#define FL_KOFF FQS_SZ
#define FL_VOFF (FQS_SZ + 3 * FKS_STR)
#define FLASH_SMEM ((FQS_SZ + 3 * FKS_STR + 3 * FVS_STR) * 2)   // 87040 B
#define NTILE (SEQ / KT)

__global__ __launch_bounds__(256, 2) void flash_kernel(
    const __half* __restrict__ Qg_, const __half* __restrict__ Kg_,
    const __half* __restrict__ qkvlin, __half* __restrict__ attn)
{
    extern __shared__ __half fsm[];
    __half* Qs = fsm;
    const uint32_t qs_u = (uint32_t)__cvta_generic_to_shared(Qs);
    const uint32_t ks_u = qs_u + FL_KOFF * 2;
    const uint32_t vs_u = qs_u + FL_VOFF * 2;

    const int qblk = blockIdx.x, bh = blockIdx.y;
    const int b = bh >> 4, h = bh & 15;
    const int tid = threadIdx.x, lane = tid & 31, wid = tid >> 5;
    const int grp = lane >> 2, tig = lane & 3;

    const __half* Qg = Qg_ + ((long long)bh * SEQ + qblk * QROWS) * DHEAD;
    const __half* Kg = Kg_ + (long long)bh * SEQ * DHEAD;
    const __half* Vg = qkvlin + ((long long)b * SEQ) * VSTRIDE + 2 * INNER + h * DHEAD;

    auto issue = [&](int it, int buf) {
        #pragma unroll
        for (int i = 0; i < 2; i++) {
            int ch = tid + 256 * i;
            int row = ch >> 4, cc = (ch & 15) * 8;
            uint32_t d = ks_u + (buf * FKS_STR + row * FPK + cc) * 2;
            CPA16(d, Kg + (long long)(it * KT + row) * DHEAD + cc);
        }
        #pragma unroll
        for (int i = 0; i < 2; i++) {
            int ch = tid + 256 * i;
            int row = ch >> 4, cc = (ch & 15) * 8;
            uint32_t d = vs_u + (buf * FVS_STR + row * FPK + cc) * 2;
            CPA16(d, Vg + (long long)(it * KT + row) * VSTRIDE + cc);
        }
        asm volatile("cp.async.commit_group;");
    };

    issue(0, 0);
    issue(1, 1);

    #pragma unroll
    for (int i = 0; i < 8; i++) {
        int ch = tid + 256 * i;
        int row = ch >> 4, cc = (ch & 15) * 8;
        *(uint4*)&Qs[row * FPQ + cc] = *(const uint4*)(Qg + row * DHEAD + cc);
    }

    float o[16][4];
    #pragma unroll
    for (int f = 0; f < 16; f++)
        #pragma unroll
        for (int r = 0; r < 4; r++) o[f][r] = 0.0f;
    float l0 = 0.0f, l1 = 0.0f;

    for (int it = 0; it < NTILE; it++) {
        if (it < NTILE - 1) asm volatile("cp.async.wait_group 1;");
        else                asm volatile("cp.async.wait_group 0;");
        __syncthreads();
        if (it + 2 < NTILE) issue(it + 2, (it + 2) % 3);

        const uint32_t kb = ks_u + (it % 3) * FKS_STR * 2;
        const uint32_t vb = vs_u + (it % 3) * FVS_STR * 2;

        // ---- S = Q @ K^T : 16 rows x 32 keys per warp ----
        float sc[4][4];
        #pragma unroll
        for (int f = 0; f < 4; f++)
            #pragma unroll
            for (int r = 0; r < 4; r++) sc[f][r] = 0.0f;

        #pragma unroll
        for (int s = 0; s < 8; s++) {
            const int ks = s * 16;
            uint32_t a0, a1, a2, a3;
            {
                int row = wid * 16 + (lane & 15);
                uint32_t ad = qs_u + (row * FPQ + ks + ((lane >> 4) * 8)) * 2;
                LDSM4(a0, a1, a2, a3, ad);
            }
            #pragma unroll
            for (int pf = 0; pf < 2; pf++) {
                int j = lane >> 3;
                int krow = pf * 16 + ((j >> 1) * 8) + (lane & 7);
                uint32_t bd = kb + (krow * FPK + ks + ((j & 1) * 8)) * 2;
                uint32_t r0, r1, r2, r3;
                LDSM4(r0, r1, r2, r3, bd);
                MMA_F16(sc[2 * pf],     a0, a1, a2, a3, r0, r1);
                MMA_F16(sc[2 * pf + 1], a0, a1, a2, a3, r2, r3);
            }
        }

        // ---- softmax numerator via ex2.approx.f16x2 (no max shift) ----
        uint32_t pu[4][2];
        float rs0 = 0.0f, rs1 = 0.0f;
        #pragma unroll
        for (int f = 0; f < 4; f++) {
            uint32_t h01 = pack2(sc[f][0] * L2E, sc[f][1] * L2E);
            uint32_t h23 = pack2(sc[f][2] * L2E, sc[f][3] * L2E);
            asm("ex2.approx.f16x2 %0, %1;" : "=r"(h01) : "r"(h01));
            asm("ex2.approx.f16x2 %0, %1;" : "=r"(h23) : "r"(h23));
            pu[f][0] = h01; pu[f][1] = h23;
            float2 p01 = __half22float2(*reinterpret_cast<__half2*>(&h01));
            float2 p23 = __half22float2(*reinterpret_cast<__half2*>(&h23));
            rs0 += p01.x + p01.y;
            rs1 += p23.x + p23.y;
        }
        rs0 += __shfl_xor_sync(0xffffffffu, rs0, 1);
        rs0 += __shfl_xor_sync(0xffffffffu, rs0, 2);
        rs1 += __shfl_xor_sync(0xffffffffu, rs1, 1);
        rs1 += __shfl_xor_sync(0xffffffffu, rs1, 2);
        l0 += rs0; l1 += rs1;

        // ---- O += P @ V : V natural [key][d], trans ldmatrix ----
        #pragma unroll
        for (int s = 0; s < 2; s++) {
            uint32_t a0 = pu[2 * s][0];
            uint32_t a1 = pu[2 * s][1];
            uint32_t a2 = pu[2 * s + 1][0];
            uint32_t a3 = pu[2 * s + 1][1];
            #pragma unroll
            for (int pf = 0; pf < 8; pf++) {
                int row = s * 16 + (lane & 15);
                int col = pf * 16 + ((lane >> 4) * 8);
                uint32_t bd = vb + (row * FPK + col) * 2;
                uint32_t r0, r1, r2, r3;
                LDSM4T(r0, r1, r2, r3, bd);
                MMA_F16(o[2 * pf],     a0, a1, a2, a3, r0, r1);
                MMA_F16(o[2 * pf + 1], a0, a1, a2, a3, r2, r3);
            }
        }
    }

    float inv0 = 1.0f / l0, inv1 = 1.0f / l1;
    int nrow = qblk * QROWS + 16 * wid + grp;
    __half* outp = attn + ((long long)(b * SEQ + nrow)) * INNER + h * DHEAD;
    #pragma unroll
    for (int f = 0; f < 16; f++) {
        int col = 8 * f + 2 * tig;
        *(__half2*)(outp + col) = __floats2half2_rn(o[f][0] * inv0, o[f][1] * inv0);
        *(__half2*)(outp + (long long)8 * INNER + col) =
            __floats2half2_rn(o[f][2] * inv1, o[f][3] * inv1);
    }
}

// ---------------- launch ----------------
extern "C" void kernel_launch(void* const* d_in, const int* in_sizes, int n_in,
                              void* d_out, int out_size)
{
    const float* x   = (const float*)d_in[0];
    const float* rot = (const float*)d_in[1];
    const float* Wq  = (const float*)d_in[2];
    const float* Wkv = (const float*)d_in[3];
    const float* Wo  = (const float*)d_in[4];
    const float* bo  = (const float*)d_in[5];
    float* out = (float*)d_out;

    __half *xh, *Wqkvh, *Woh, *qkvlin, *Qh, *Kh, *attnh;
    float *ctab, *stab;
    cudaGetSymbolAddress((void**)&xh,     g_xh);
    cudaGetSymbolAddress((void**)&Wqkvh,  g_Wqkvh);
    cudaGetSymbolAddress((void**)&Woh,    g_Woh);
    cudaGetSymbolAddress((void**)&ctab,   g_ctab);
    cudaGetSymbolAddress((void**)&stab,   g_stab);
    cudaGetSymbolAddress((void**)&qkvlin, g_qkvlin);
    cudaGetSymbolAddress((void**)&Qh,     g_Qh);
    cudaGetSymbolAddress((void**)&Kh,     g_Kh);
    cudaGetSymbolAddress((void**)&attnh,  g_attnh);

    cudaFuncSetAttribute(flash_kernel,
                         cudaFuncAttributeMaxDynamicSharedMemorySize, FLASH_SMEM);
    cudaFuncSetAttribute(hgemm_kernel<0>,
                         cudaFuncAttributeMaxDynamicSharedMemorySize, HG_SMEM);
    cudaFuncSetAttribute(hgemm_kernel<1>,
                         cudaFuncAttributeMaxDynamicSharedMemorySize, HG_SMEM);

    dim3 blk(256);
    const int M = BATCH * SEQ;   // 4096

    // 0) convert all inputs to fp16 (Wq/Wkv interleaved into combined [K,3N]); rotary tables
    cvt4_kernel<<<CV_TOT / (256 * 4), blk>>>(
        (const float4*)x,   (uint2*)xh,
        (const float4*)Wq,  (const float4*)Wkv, (uint2*)Wqkvh,
        (const float4*)Wo,  (uint2*)Woh);
    rottab_kernel<<<(SEQ * DHEAD) / 256, blk>>>(rot, ctab, stab);

    // 1) qkv_lin = xh @ [Wq|Wkv]   (fp16 out, single launch, N = 3*INNER)
    hgemm_kernel<1><<<dim3(3 * INNER / 128, M / 128), blk, HG_SMEM>>>(
        xh, Wqkvh, qkvlin, M, 3 * INNER, DIM, 3 * INNER, nullptr);

    // 2) rotary + head split -> Qh, Kh (wide: 16 B per thread per tensor)
    rotary_kernel<<<(BATCH * SEQ * HEADS * 16) / 256, blk>>>(qkvlin, ctab, stab, Qh, Kh);

    // 3) fused attention -> attnh; V from qkvlin
    flash_kernel<<<dim3(SEQ / QROWS, BH), blk, FLASH_SMEM>>>(Qh, Kh, qkvlin, attnh);

    // 4) out = attnh @ Woh + bo  (fp32 out)
    hgemm_kernel<0><<<dim3(DIM / 128, M / 128), blk, HG_SMEM>>>(
        attnh, Woh, out, M, DIM, INNER, DIM, bo);
}